// round 2
// baseline (speedup 1.0000x reference)
#include <cuda_runtime.h>
#include <math.h>

#define BB 4
#define LL 4096
#define DD 1024
#define NT (BB*LL)          // 16384 tokens
#define NF 513              // rfft bins
#define FS 520              // float2 row stride (alignment pad)
#define NCH 64              // scan chunks
#define CHL (LL/NCH)        // 64 steps per chunk
#define COMPS (NF*2)        // 1026 float components per row

// ---------- scratch (static device memory; no allocations) ----------
__device__ float  g_keys[NT*DD];
__device__ float  g_vals[NT*DD];
__device__ float2 g_Kf[NT*FS];
__device__ float2 g_P [NT*FS];
__device__ float  g_aux[BB*NCH*COMPS];
__device__ float  g_rln[NT*DD];
__device__ float2 g_twid[512];

// ---------- twiddle init (fp64 for accuracy) ----------
__global__ void init_twid() {
    int t = threadIdx.x;
    double a = -2.0 * M_PI * (double)t / 1024.0;
    g_twid[t] = make_float2((float)cos(a), (float)sin(a));
}

__device__ __forceinline__ float2 cmul(float2 a, float2 b) {
    return make_float2(a.x*b.x - a.y*b.y, a.x*b.y + a.y*b.x);
}

// ---------- 1024-point Stockham complex FFT, 512 threads ----------
// Caller must __syncthreads() after filling s0. Result lands back in s0.
__device__ __forceinline__ void fft1024(float2* s0, float2* s1, int tid, bool inverse) {
    float2* src = s0;
    float2* dst = s1;
    #pragma unroll
    for (int m = 1; m <= 512; m <<= 1) {
        int jm = tid & ~(m - 1);
        float2 u = src[tid];
        float2 v = src[tid + 512];
        float2 w = g_twid[jm];
        float wy = inverse ? -w.y : w.y;
        float2 sum = make_float2(u.x + v.x, u.y + v.y);
        float2 dif = make_float2(u.x - v.x, u.y - v.y);
        float2 dw  = make_float2(dif.x*w.x - dif.y*wy, dif.x*wy + dif.y*w.x);
        dst[tid + jm]     = sum;
        dst[tid + jm + m] = dw;
        __syncthreads();
        float2* tp = src; src = dst; dst = tp;
    }
}

// ---------- SGEMM: C[m,n] = A[m,:]·W[n,:] + bias[n] (+resid)  (K=N=1024, M=16384) ----------
__global__ void __launch_bounds__(256) sgemm_nt(
    const float* __restrict__ A, const float* __restrict__ W,
    const float* __restrict__ bias, const float* __restrict__ resid,
    float* __restrict__ C)
{
    const int K = 1024, N = 1024;
    __shared__ float As[16][68];
    __shared__ float Bs[16][68];
    int tid = threadIdx.x;
    int m0 = blockIdx.y * 64, n0 = blockIdx.x * 64;
    int lr = tid >> 2;          // 0..63 tile row
    int lk = (tid & 3) * 4;     // 0,4,8,12 k offset
    int tx = tid & 15, ty = tid >> 4;

    float acc[4][4];
    #pragma unroll
    for (int i = 0; i < 4; i++)
        #pragma unroll
        for (int j = 0; j < 4; j++) acc[i][j] = 0.f;

    for (int k0 = 0; k0 < K; k0 += 16) {
        float4 a4 = *(const float4*)(A + (size_t)(m0 + lr) * K + k0 + lk);
        float4 b4 = *(const float4*)(W + (size_t)(n0 + lr) * K + k0 + lk);
        As[lk+0][lr] = a4.x; As[lk+1][lr] = a4.y; As[lk+2][lr] = a4.z; As[lk+3][lr] = a4.w;
        Bs[lk+0][lr] = b4.x; Bs[lk+1][lr] = b4.y; Bs[lk+2][lr] = b4.z; Bs[lk+3][lr] = b4.w;
        __syncthreads();
        #pragma unroll
        for (int kk = 0; kk < 16; kk++) {
            float4 av = *(const float4*)&As[kk][ty * 4];
            float4 bv = *(const float4*)&Bs[kk][tx * 4];
            float a[4] = {av.x, av.y, av.z, av.w};
            float b[4] = {bv.x, bv.y, bv.z, bv.w};
            #pragma unroll
            for (int i = 0; i < 4; i++)
                #pragma unroll
                for (int j = 0; j < 4; j++)
                    acc[i][j] = fmaf(a[i], b[j], acc[i][j]);
        }
        __syncthreads();
    }

    float4 bia = *(const float4*)&bias[n0 + tx * 4];
    #pragma unroll
    for (int i = 0; i < 4; i++) {
        int m = m0 + ty * 4 + i;
        size_t off = (size_t)m * N + n0 + tx * 4;
        float4 v;
        v.x = acc[i][0] + bia.x; v.y = acc[i][1] + bia.y;
        v.z = acc[i][2] + bia.z; v.w = acc[i][3] + bia.w;
        if (resid) {
            float4 r = *(const float4*)(resid + off);
            v.x += r.x; v.y += r.y; v.z += r.z; v.w += r.w;
        }
        *(float4*)(C + off) = v;
    }
}

// ---------- per-token: normalize key, FFT key & value, store Kf and P = Kf*Vf ----------
__global__ void __launch_bounds__(512) fwd_kernel() {
    __shared__ float2 s0[1024];
    __shared__ float2 s1[1024];
    __shared__ float red[16];
    int t = blockIdx.x, tid = threadIdx.x;

    const float* kr = g_keys + (size_t)t * DD;
    float k0 = kr[tid], k1 = kr[tid + 512];
    float ss = k0*k0 + k1*k1;
    #pragma unroll
    for (int o = 16; o; o >>= 1) ss += __shfl_xor_sync(0xffffffffu, ss, o);
    if ((tid & 31) == 0) red[tid >> 5] = ss;
    __syncthreads();
    if (tid < 16) {
        float v = red[tid];
        #pragma unroll
        for (int o = 8; o; o >>= 1) v += __shfl_xor_sync(0xffffu, v, o);
        if (tid == 0) red[0] = v;
    }
    __syncthreads();
    float scl = 1.0f / fmaxf(sqrtf(red[0]), 1e-12f);

    s0[tid]       = make_float2(k0 * scl, 0.f);
    s0[tid + 512] = make_float2(k1 * scl, 0.f);
    __syncthreads();
    fft1024(s0, s1, tid, false);

    float2 kfa = s0[tid];
    float2 kf512 = make_float2(0.f, 0.f);
    if (tid == 0) kf512 = s0[512];
    g_Kf[(size_t)t * FS + tid] = kfa;
    if (tid == 0) g_Kf[(size_t)t * FS + 512] = kf512;
    __syncthreads();

    const float* vr = g_vals + (size_t)t * DD;
    s0[tid]       = make_float2(vr[tid], 0.f);
    s0[tid + 512] = make_float2(vr[tid + 512], 0.f);
    __syncthreads();
    fft1024(s0, s1, tid, false);

    g_P[(size_t)t * FS + tid] = cmul(kfa, s0[tid]);
    if (tid == 0) g_P[(size_t)t * FS + 512] = cmul(kf512, s0[512]);
}

// ---------- blocked scan over sequence (pass 1: intra-chunk cumsum + chunk totals) ----------
__global__ void __launch_bounds__(256) scan1() {
    int idx = blockIdx.x * blockDim.x + threadIdx.x;   // < 4*64*1026
    int comp  = idx % COMPS;
    int rest  = idx / COMPS;
    int chunk = rest % NCH;
    int b     = rest / NCH;
    float* Pf = (float*)g_P;
    size_t base = (size_t)(b * LL + chunk * CHL) * (FS * 2) + comp;
    float acc = 0.f;
    #pragma unroll 4
    for (int s = 0; s < CHL; s++) {
        acc += Pf[base];
        Pf[base] = acc;
        base += FS * 2;
    }
    g_aux[(b * NCH + chunk) * COMPS + comp] = acc;
}

// ---------- pass 2: add exclusive chunk offsets ----------
__global__ void __launch_bounds__(256) scan2() {
    int idx = blockIdx.x * blockDim.x + threadIdx.x;
    int comp  = idx % COMPS;
    int rest  = idx / COMPS;
    int chunk = rest % NCH;
    int b     = rest / NCH;
    if (chunk == 0) return;
    float off = 0.f;
    for (int c = 0; c < chunk; c++) off += g_aux[(b * NCH + c) * COMPS + comp];
    float* Pf = (float*)g_P;
    size_t base = (size_t)(b * LL + chunk * CHL) * (FS * 2) + comp;
    #pragma unroll 4
    for (int s = 0; s < CHL; s++) {
        Pf[base] += off;
        base += FS * 2;
    }
}

// ---------- per-token: S = cumP*conj(Kf), inverse FFT, /sqrt(pos), LayerNorm ----------
__global__ void __launch_bounds__(512) inv_kernel(const float* __restrict__ ln_g,
                                                  const float* __restrict__ ln_b) {
    __shared__ float2 s0[1024];
    __shared__ float2 s1[1024];
    __shared__ float red[32];
    int t = blockIdx.x, tid = threadIdx.x;
    size_t fb = (size_t)t * FS;

    float2 kf = g_Kf[fb + tid];
    float2 mp = g_P[fb + tid];
    float2 S = make_float2(mp.x*kf.x + mp.y*kf.y, mp.y*kf.x - mp.x*kf.y);
    s0[tid] = S;
    if (tid) {
        s0[1024 - tid] = make_float2(S.x, -S.y);
    } else {
        float2 kf5 = g_Kf[fb + 512];
        float2 mp5 = g_P[fb + 512];
        s0[512] = make_float2(mp5.x*kf5.x + mp5.y*kf5.y, mp5.y*kf5.x - mp5.x*kf5.y);
    }
    __syncthreads();
    fft1024(s0, s1, tid, true);   // inverse (unscaled)

    int pos = (t & (LL - 1)) + 1;
    float scale = rsqrtf((float)pos) * (1.0f / 1024.0f);
    float r0 = s0[tid].x * scale;
    float r1 = s0[tid + 512].x * scale;

    float sm = r0 + r1;
    float sq = r0*r0 + r1*r1;
    #pragma unroll
    for (int o = 16; o; o >>= 1) {
        sm += __shfl_xor_sync(0xffffffffu, sm, o);
        sq += __shfl_xor_sync(0xffffffffu, sq, o);
    }
    if ((tid & 31) == 0) { red[tid >> 5] = sm; red[16 + (tid >> 5)] = sq; }
    __syncthreads();
    if (tid < 16) {
        float a = red[tid], q = red[16 + tid];
        #pragma unroll
        for (int o = 8; o; o >>= 1) {
            a += __shfl_xor_sync(0xffffu, a, o);
            q += __shfl_xor_sync(0xffffu, q, o);
        }
        if (tid == 0) { red[0] = a; red[16] = q; }
    }
    __syncthreads();
    float mu  = red[0] * (1.0f / 1024.0f);
    float var = red[16] * (1.0f / 1024.0f) - mu * mu;
    float rstd = rsqrtf(var + 1e-5f);

    size_t ob = (size_t)t * DD;
    g_rln[ob + tid]       = (r0 - mu) * rstd * ln_g[tid]       + ln_b[tid];
    g_rln[ob + tid + 512] = (r1 - mu) * rstd * ln_g[tid + 512] + ln_b[tid + 512];
}

// ---------- launch ----------
extern "C" void kernel_launch(void* const* d_in, const int* in_sizes, int n_in,
                              void* d_out, int out_size) {
    const float* x    = (const float*)d_in[0];
    const float* Wk   = (const float*)d_in[1];
    const float* bk   = (const float*)d_in[2];
    const float* Wv   = (const float*)d_in[3];
    const float* bv   = (const float*)d_in[4];
    const float* ln_g = (const float*)d_in[5];
    const float* ln_b = (const float*)d_in[6];
    const float* Wo   = (const float*)d_in[7];
    const float* bo   = (const float*)d_in[8];
    float* out = (float*)d_out;

    float *keys, *vals, *rln;
    cudaGetSymbolAddress((void**)&keys, g_keys);
    cudaGetSymbolAddress((void**)&vals, g_vals);
    cudaGetSymbolAddress((void**)&rln,  g_rln);

    init_twid<<<1, 512>>>();

    dim3 gg(16, 256);   // N/64 x M/64
    sgemm_nt<<<gg, 256>>>(x, Wk, bk, nullptr, keys);
    sgemm_nt<<<gg, 256>>>(x, Wv, bv, nullptr, vals);

    fwd_kernel<<<NT, 512>>>();

    scan1<<<(BB * NCH * COMPS) / 256, 256>>>();
    scan2<<<(BB * NCH * COMPS) / 256, 256>>>();

    inv_kernel<<<NT, 512>>>(ln_g, ln_b);

    sgemm_nt<<<gg, 256>>>(rln, Wo, bo, x, out);
}

// round 3
// speedup vs baseline: 1.0288x; 1.0288x over previous
#include <cuda_runtime.h>
#include <math.h>

#define BB 4
#define LL 4096
#define DD 1024
#define NT (BB*LL)          // 16384 tokens
#define NF 513              // rfft bins
#define FS 520              // float2 row stride (alignment pad)
#define NCH 64              // scan chunks
#define CHL (LL/NCH)        // 64 steps per chunk
#define COMPS (NF*2)        // 1026 float components per row

// ---------- scratch (static device memory; no allocations) ----------
__device__ float  g_keys[NT*DD];
__device__ float  g_vals[NT*DD];
__device__ float2 g_Kf[NT*FS];
__device__ float2 g_P [NT*FS];
__device__ float  g_aux[BB*NCH*COMPS];
__device__ float  g_rln[NT*DD];
__device__ float2 g_twid[512];

// ---------- twiddle init (fp64 for accuracy) ----------
__global__ void init_twid() {
    int t = threadIdx.x;
    double a = -2.0 * M_PI * (double)t / 1024.0;
    g_twid[t] = make_float2((float)cos(a), (float)sin(a));
}

__device__ __forceinline__ float2 cmul(float2 a, float2 b) {
    return make_float2(a.x*b.x - a.y*b.y, a.x*b.y + a.y*b.x);
}

// ---------- packed f32x2 helpers (Blackwell FFMA2 pipe; PTX-only) ----------
__device__ __forceinline__ unsigned long long pack2(float lo, float hi) {
    unsigned long long r;
    asm("mov.b64 %0, {%1, %2};" : "=l"(r) : "f"(lo), "f"(hi));
    return r;
}
__device__ __forceinline__ void ffma2(unsigned long long& d,
                                      unsigned long long a,
                                      unsigned long long b) {
    asm("fma.rn.f32x2 %0, %1, %2, %0;" : "+l"(d) : "l"(a), "l"(b));
}
__device__ __forceinline__ float2 unpack2(unsigned long long v) {
    float lo, hi;
    asm("mov.b64 {%0, %1}, %2;" : "=f"(lo), "=f"(hi) : "l"(v));
    return make_float2(lo, hi);
}

// ---------- SGEMM via FFMA2: C[m,n] = A[m,:]·W[n,:] + bias[n] (+resid) ----------
// 128x128 tile, K-tile 16, 256 threads, 8x8 outputs/thread, double-buffered smem.
__global__ void __launch_bounds__(256) sgemm_nt(
    const float* __restrict__ A, const float* __restrict__ W,
    const float* __restrict__ bias, const float* __restrict__ resid,
    float* __restrict__ C)
{
    const int K = 1024, N = 1024;
    __shared__ float As[2][16][132];
    __shared__ float Bs[2][16][132];
    int tid = threadIdx.x;
    int m0 = blockIdx.y * 128, n0 = blockIdx.x * 128;
    int tx = tid & 15, ty = tid >> 4;

    // load slots: thread handles rows r and r+64, k-quad kq
    int lr = tid >> 2;         // 0..63
    int lk = (tid & 3) * 4;    // 0,4,8,12

    unsigned long long acc[8][4];
    #pragma unroll
    for (int i = 0; i < 8; i++)
        #pragma unroll
        for (int j = 0; j < 4; j++) acc[i][j] = 0ull;

    const float* Ap0 = A + (size_t)(m0 + lr) * K + lk;
    const float* Ap1 = A + (size_t)(m0 + lr + 64) * K + lk;
    const float* Bp0 = W + (size_t)(n0 + lr) * K + lk;
    const float* Bp1 = W + (size_t)(n0 + lr + 64) * K + lk;

    float4 a0 = *(const float4*)(Ap0);
    float4 a1 = *(const float4*)(Ap1);
    float4 b0 = *(const float4*)(Bp0);
    float4 b1 = *(const float4*)(Bp1);

    #pragma unroll
    for (int kt = 0; kt < 64; kt++) {
        int cur = kt & 1, nxt = cur ^ 1;
        // stage current regs into smem buffer `cur`
        As[cur][lk+0][lr]    = a0.x; As[cur][lk+1][lr]    = a0.y;
        As[cur][lk+2][lr]    = a0.z; As[cur][lk+3][lr]    = a0.w;
        As[cur][lk+0][lr+64] = a1.x; As[cur][lk+1][lr+64] = a1.y;
        As[cur][lk+2][lr+64] = a1.z; As[cur][lk+3][lr+64] = a1.w;
        Bs[cur][lk+0][lr]    = b0.x; Bs[cur][lk+1][lr]    = b0.y;
        Bs[cur][lk+2][lr]    = b0.z; Bs[cur][lk+3][lr]    = b0.w;
        Bs[cur][lk+0][lr+64] = b1.x; Bs[cur][lk+1][lr+64] = b1.y;
        Bs[cur][lk+2][lr+64] = b1.z; Bs[cur][lk+3][lr+64] = b1.w;
        __syncthreads();

        // prefetch next k-tile from global
        if (kt < 63) {
            int ko = (kt + 1) * 16;
            a0 = *(const float4*)(Ap0 + ko);
            a1 = *(const float4*)(Ap1 + ko);
            b0 = *(const float4*)(Bp0 + ko);
            b1 = *(const float4*)(Bp1 + ko);
        }

        #pragma unroll
        for (int kk = 0; kk < 16; kk++) {
            float4 av0 = *(const float4*)&As[cur][kk][ty * 8];
            float4 av1 = *(const float4*)&As[cur][kk][ty * 8 + 4];
            float4 bv0 = *(const float4*)&Bs[cur][kk][tx * 8];
            float4 bv1 = *(const float4*)&Bs[cur][kk][tx * 8 + 4];
            unsigned long long bp[4];
            bp[0] = pack2(bv0.x, bv0.y); bp[1] = pack2(bv0.z, bv0.w);
            bp[2] = pack2(bv1.x, bv1.y); bp[3] = pack2(bv1.z, bv1.w);
            float av[8] = {av0.x, av0.y, av0.z, av0.w, av1.x, av1.y, av1.z, av1.w};
            #pragma unroll
            for (int i = 0; i < 8; i++) {
                unsigned long long ai = pack2(av[i], av[i]);
                #pragma unroll
                for (int j = 0; j < 4; j++) ffma2(acc[i][j], ai, bp[j]);
            }
        }
        __syncthreads();
        (void)nxt;
    }

    // epilogue
    float4 bia0 = *(const float4*)&bias[n0 + tx * 8];
    float4 bia1 = *(const float4*)&bias[n0 + tx * 8 + 4];
    #pragma unroll
    for (int i = 0; i < 8; i++) {
        int m = m0 + ty * 8 + i;
        size_t off = (size_t)m * N + n0 + tx * 8;
        float2 o0 = unpack2(acc[i][0]);
        float2 o1 = unpack2(acc[i][1]);
        float2 o2 = unpack2(acc[i][2]);
        float2 o3 = unpack2(acc[i][3]);
        float4 v0 = make_float4(o0.x + bia0.x, o0.y + bia0.y, o1.x + bia0.z, o1.y + bia0.w);
        float4 v1 = make_float4(o2.x + bia1.x, o2.y + bia1.y, o3.x + bia1.z, o3.y + bia1.w);
        if (resid) {
            float4 r0 = *(const float4*)(resid + off);
            float4 r1 = *(const float4*)(resid + off + 4);
            v0.x += r0.x; v0.y += r0.y; v0.z += r0.z; v0.w += r0.w;
            v1.x += r1.x; v1.y += r1.y; v1.z += r1.z; v1.w += r1.w;
        }
        *(float4*)(C + off)     = v0;
        *(float4*)(C + off + 4) = v1;
    }
}

// ---------- 1024-point Stockham complex FFT, 512 threads ----------
__device__ __forceinline__ void fft1024(float2* s0, float2* s1, int tid, bool inverse) {
    float2* src = s0;
    float2* dst = s1;
    #pragma unroll
    for (int m = 1; m <= 512; m <<= 1) {
        int jm = tid & ~(m - 1);
        float2 u = src[tid];
        float2 v = src[tid + 512];
        float2 w = g_twid[jm];
        float wy = inverse ? -w.y : w.y;
        float2 sum = make_float2(u.x + v.x, u.y + v.y);
        float2 dif = make_float2(u.x - v.x, u.y - v.y);
        float2 dw  = make_float2(dif.x*w.x - dif.y*wy, dif.x*wy + dif.y*w.x);
        dst[tid + jm]     = sum;
        dst[tid + jm + m] = dw;
        __syncthreads();
        float2* tp = src; src = dst; dst = tp;
    }
}

// ---------- per-token: normalize key, FFT key & value, store Kf and P = Kf*Vf ----------
__global__ void __launch_bounds__(512) fwd_kernel() {
    __shared__ float2 s0[1024];
    __shared__ float2 s1[1024];
    __shared__ float red[16];
    int t = blockIdx.x, tid = threadIdx.x;

    const float* kr = g_keys + (size_t)t * DD;
    float k0 = kr[tid], k1 = kr[tid + 512];
    float ss = k0*k0 + k1*k1;
    #pragma unroll
    for (int o = 16; o; o >>= 1) ss += __shfl_xor_sync(0xffffffffu, ss, o);
    if ((tid & 31) == 0) red[tid >> 5] = ss;
    __syncthreads();
    if (tid < 16) {
        float v = red[tid];
        #pragma unroll
        for (int o = 8; o; o >>= 1) v += __shfl_xor_sync(0xffffu, v, o);
        if (tid == 0) red[0] = v;
    }
    __syncthreads();
    float scl = 1.0f / fmaxf(sqrtf(red[0]), 1e-12f);

    s0[tid]       = make_float2(k0 * scl, 0.f);
    s0[tid + 512] = make_float2(k1 * scl, 0.f);
    __syncthreads();
    fft1024(s0, s1, tid, false);

    float2 kfa = s0[tid];
    float2 kf512 = make_float2(0.f, 0.f);
    if (tid == 0) kf512 = s0[512];
    g_Kf[(size_t)t * FS + tid] = kfa;
    if (tid == 0) g_Kf[(size_t)t * FS + 512] = kf512;
    __syncthreads();

    const float* vr = g_vals + (size_t)t * DD;
    s0[tid]       = make_float2(vr[tid], 0.f);
    s0[tid + 512] = make_float2(vr[tid + 512], 0.f);
    __syncthreads();
    fft1024(s0, s1, tid, false);

    g_P[(size_t)t * FS + tid] = cmul(kfa, s0[tid]);
    if (tid == 0) g_P[(size_t)t * FS + 512] = cmul(kf512, s0[512]);
}

// ---------- blocked scan over sequence (pass 1) ----------
__global__ void __launch_bounds__(256) scan1() {
    int idx = blockIdx.x * blockDim.x + threadIdx.x;
    int comp  = idx % COMPS;
    int rest  = idx / COMPS;
    int chunk = rest % NCH;
    int b     = rest / NCH;
    float* Pf = (float*)g_P;
    size_t base = (size_t)(b * LL + chunk * CHL) * (FS * 2) + comp;
    float acc = 0.f;
    #pragma unroll 4
    for (int s = 0; s < CHL; s++) {
        acc += Pf[base];
        Pf[base] = acc;
        base += FS * 2;
    }
    g_aux[(b * NCH + chunk) * COMPS + comp] = acc;
}

// ---------- pass 2: add exclusive chunk offsets ----------
__global__ void __launch_bounds__(256) scan2() {
    int idx = blockIdx.x * blockDim.x + threadIdx.x;
    int comp  = idx % COMPS;
    int rest  = idx / COMPS;
    int chunk = rest % NCH;
    int b     = rest / NCH;
    if (chunk == 0) return;
    float off = 0.f;
    for (int c = 0; c < chunk; c++) off += g_aux[(b * NCH + c) * COMPS + comp];
    float* Pf = (float*)g_P;
    size_t base = (size_t)(b * LL + chunk * CHL) * (FS * 2) + comp;
    #pragma unroll 4
    for (int s = 0; s < CHL; s++) {
        Pf[base] += off;
        base += FS * 2;
    }
}

// ---------- per-token: S = cumP*conj(Kf), inverse FFT, /sqrt(pos), LayerNorm ----------
__global__ void __launch_bounds__(512) inv_kernel(const float* __restrict__ ln_g,
                                                  const float* __restrict__ ln_b) {
    __shared__ float2 s0[1024];
    __shared__ float2 s1[1024];
    __shared__ float red[32];
    int t = blockIdx.x, tid = threadIdx.x;
    size_t fb = (size_t)t * FS;

    float2 kf = g_Kf[fb + tid];
    float2 mp = g_P[fb + tid];
    float2 S = make_float2(mp.x*kf.x + mp.y*kf.y, mp.y*kf.x - mp.x*kf.y);
    s0[tid] = S;
    if (tid) {
        s0[1024 - tid] = make_float2(S.x, -S.y);
    } else {
        float2 kf5 = g_Kf[fb + 512];
        float2 mp5 = g_P[fb + 512];
        s0[512] = make_float2(mp5.x*kf5.x + mp5.y*kf5.y, mp5.y*kf5.x - mp5.x*kf5.y);
    }
    __syncthreads();
    fft1024(s0, s1, tid, true);

    int pos = (t & (LL - 1)) + 1;
    float scale = rsqrtf((float)pos) * (1.0f / 1024.0f);
    float r0 = s0[tid].x * scale;
    float r1 = s0[tid + 512].x * scale;

    float sm = r0 + r1;
    float sq = r0*r0 + r1*r1;
    #pragma unroll
    for (int o = 16; o; o >>= 1) {
        sm += __shfl_xor_sync(0xffffffffu, sm, o);
        sq += __shfl_xor_sync(0xffffffffu, sq, o);
    }
    if ((tid & 31) == 0) { red[tid >> 5] = sm; red[16 + (tid >> 5)] = sq; }
    __syncthreads();
    if (tid < 16) {
        float a = red[tid], q = red[16 + tid];
        #pragma unroll
        for (int o = 8; o; o >>= 1) {
            a += __shfl_xor_sync(0xffffu, a, o);
            q += __shfl_xor_sync(0xffffu, q, o);
        }
        if (tid == 0) { red[0] = a; red[16] = q; }
    }
    __syncthreads();
    float mu  = red[0] * (1.0f / 1024.0f);
    float var = red[16] * (1.0f / 1024.0f) - mu * mu;
    float rstd = rsqrtf(var + 1e-5f);

    size_t ob = (size_t)t * DD;
    g_rln[ob + tid]       = (r0 - mu) * rstd * ln_g[tid]       + ln_b[tid];
    g_rln[ob + tid + 512] = (r1 - mu) * rstd * ln_g[tid + 512] + ln_b[tid + 512];
}

// ---------- launch ----------
extern "C" void kernel_launch(void* const* d_in, const int* in_sizes, int n_in,
                              void* d_out, int out_size) {
    const float* x    = (const float*)d_in[0];
    const float* Wk   = (const float*)d_in[1];
    const float* bk   = (const float*)d_in[2];
    const float* Wv   = (const float*)d_in[3];
    const float* bv   = (const float*)d_in[4];
    const float* ln_g = (const float*)d_in[5];
    const float* ln_b = (const float*)d_in[6];
    const float* Wo   = (const float*)d_in[7];
    const float* bo   = (const float*)d_in[8];
    float* out = (float*)d_out;

    float *keys, *vals, *rln;
    cudaGetSymbolAddress((void**)&keys, g_keys);
    cudaGetSymbolAddress((void**)&vals, g_vals);
    cudaGetSymbolAddress((void**)&rln,  g_rln);

    init_twid<<<1, 512>>>();

    dim3 gg(8, 128);   // N/128 x M/128
    sgemm_nt<<<gg, 256>>>(x, Wk, bk, nullptr, keys);
    sgemm_nt<<<gg, 256>>>(x, Wv, bv, nullptr, vals);

    fwd_kernel<<<NT, 512>>>();

    scan1<<<(BB * NCH * COMPS) / 256, 256>>>();
    scan2<<<(BB * NCH * COMPS) / 256, 256>>>();

    inv_kernel<<<NT, 512>>>(ln_g, ln_b);

    sgemm_nt<<<gg, 256>>>(rln, Wo, bo, x, out);
}

// round 5
// speedup vs baseline: 2.6956x; 2.6203x over previous
#include <cuda_runtime.h>
#include <cuda_bf16.h>
#include <math.h>
#include <stdint.h>

#define BB 4
#define LL 4096
#define DD 1024
#define NT (BB*LL)          // 16384 tokens
#define NF 513
#define FS 520
#define NCH 64
#define CHL (LL/NCH)
#define COMPS (NF*2)

// GEMM tiling
#define TM 128
#define TN 128
#define KC 64
#define NKC (DD/KC)         // 16
#define STG 65536           // bytes per pipeline stage (4 bufs x 16KB)
#define GEMM_SMEM (2*STG)   // 128KB

// ---------- scratch ----------
__device__ float  g_keys[NT*DD];
__device__ float  g_vals[NT*DD];
__device__ float2 g_Kf[NT*FS];
__device__ float2 g_P [NT*FS];
__device__ float  g_aux[BB*NCH*COMPS];
__device__ float2 g_twid[512];
__device__ __align__(16) __nv_bfloat16 g_xh[NT*DD],  g_xl[NT*DD];
__device__ __align__(16) __nv_bfloat16 g_rh[NT*DD],  g_rl[NT*DD];
__device__ __align__(16) __nv_bfloat16 g_Wkh[DD*DD], g_Wkl[DD*DD];
__device__ __align__(16) __nv_bfloat16 g_Wvh[DD*DD], g_Wvl[DD*DD];
__device__ __align__(16) __nv_bfloat16 g_Woh[DD*DD], g_Wol[DD*DD];

// ---------- helpers ----------
__device__ __forceinline__ uint32_t smem_u32(const void* p) {
    uint32_t a;
    asm("{ .reg .u64 t; cvta.to.shared.u64 t, %1; cvt.u32.u64 %0, t; }" : "=r"(a) : "l"(p));
    return a;
}
__device__ __forceinline__ uint32_t swz(uint32_t off) {
    return off ^ ((off >> 3) & 0x70);
}
__device__ __forceinline__ void ldm_x4(uint32_t* r, uint32_t addr) {
    asm volatile("ldmatrix.sync.aligned.m8n8.x4.shared.b16 {%0,%1,%2,%3}, [%4];"
        : "=r"(r[0]), "=r"(r[1]), "=r"(r[2]), "=r"(r[3]) : "r"(addr));
}
__device__ __forceinline__ void mma16816(float* d, const uint32_t* a, const uint32_t* b) {
    asm volatile("mma.sync.aligned.m16n8k16.row.col.f32.bf16.bf16.f32 "
        "{%0,%1,%2,%3}, {%4,%5,%6,%7}, {%8,%9}, {%0,%1,%2,%3};"
        : "+f"(d[0]), "+f"(d[1]), "+f"(d[2]), "+f"(d[3])
        : "r"(a[0]), "r"(a[1]), "r"(a[2]), "r"(a[3]), "r"(b[0]), "r"(b[1]));
}
__device__ __forceinline__ void cp16(uint32_t dst, const void* src) {
    asm volatile("cp.async.cg.shared.global [%0], [%1], 16;" :: "r"(dst), "l"(src));
}

// ---------- twiddles ----------
__global__ void init_twid() {
    int t = threadIdx.x;
    double a = -2.0 * M_PI * (double)t / 1024.0;
    g_twid[t] = make_float2((float)cos(a), (float)sin(a));
}

__device__ __forceinline__ float2 cmul(float2 a, float2 b) {
    return make_float2(a.x*b.x - a.y*b.y, a.x*b.y + a.y*b.x);
}

// ---------- fp32 -> bf16 hi/lo split ----------
__global__ void __launch_bounds__(256) conv_split(const float* __restrict__ src,
                                                  __nv_bfloat16* __restrict__ hi,
                                                  __nv_bfloat16* __restrict__ lo, int n4) {
    int i = blockIdx.x * blockDim.x + threadIdx.x;
    if (i >= n4) return;
    float4 v = ((const float4*)src)[i];
    __nv_bfloat16 h0 = __float2bfloat16_rn(v.x), h1 = __float2bfloat16_rn(v.y);
    __nv_bfloat16 h2 = __float2bfloat16_rn(v.z), h3 = __float2bfloat16_rn(v.w);
    __nv_bfloat16 l0 = __float2bfloat16_rn(v.x - __bfloat162float(h0));
    __nv_bfloat16 l1 = __float2bfloat16_rn(v.y - __bfloat162float(h1));
    __nv_bfloat16 l2 = __float2bfloat16_rn(v.z - __bfloat162float(h2));
    __nv_bfloat16 l3 = __float2bfloat16_rn(v.w - __bfloat162float(h3));
    __nv_bfloat162* H = (__nv_bfloat162*)hi;
    __nv_bfloat162* L = (__nv_bfloat162*)lo;
    H[i*2]   = __nv_bfloat162(h0, h1);
    H[i*2+1] = __nv_bfloat162(h2, h3);
    L[i*2]   = __nv_bfloat162(l0, l1);
    L[i*2+1] = __nv_bfloat162(l2, l3);
}

// ---------- HMMA bf16-split GEMM: C[m,n] = A[m,:]·W[n,:] + bias[n] (+resid) ----------
// smem stage layout: [Ah 16K][Al 16K][Bh 16K][Bl 16K], 2 stages.
__global__ void __launch_bounds__(256, 1) gemm_bf16(
    const __nv_bfloat16* __restrict__ Ah, const __nv_bfloat16* __restrict__ Al,
    const __nv_bfloat16* __restrict__ Bh, const __nv_bfloat16* __restrict__ Bl,
    const float* __restrict__ bias, const float* __restrict__ resid,
    float* __restrict__ C)
{
    extern __shared__ char smem[];
    uint32_t sb = smem_u32(smem);
    int tid = threadIdx.x, lane = tid & 31, wid = tid >> 5;
    int wm = wid >> 2, wn = wid & 3;          // 2 x 4 warp grid
    int m0 = blockIdx.y * TM, n0 = blockIdx.x * TN;

    const __nv_bfloat16* srcs[4] = {Ah, Al, Bh, Bl};
    const int rb[4] = {m0, m0, n0, n0};

    float acc[4][4][4];
    #pragma unroll
    for (int i = 0; i < 4; i++)
        #pragma unroll
        for (int j = 0; j < 4; j++)
            #pragma unroll
            for (int k = 0; k < 4; k++) acc[i][j][k] = 0.f;

    // ---- async load of one K-chunk into stage st ----
    auto load_chunk = [&](int kc, int st) {
        #pragma unroll
        for (int i = 0; i < 4; i++) {
            int ch = tid + i * 256;       // 1024 chunks of 16B per buffer
            int row = ch >> 3, j = ch & 7;
            uint32_t swo = swz((uint32_t)(row * 128 + j * 16));
            #pragma unroll
            for (int bu = 0; bu < 4; bu++) {
                const void* g = srcs[bu] + (size_t)(rb[bu] + row) * DD + kc * KC + j * 8;
                cp16(sb + st * STG + bu * 16384 + swo, g);
            }
        }
        asm volatile("cp.async.commit_group;" ::: "memory");
    };

    load_chunk(0, 0);
    load_chunk(1, 1);

    for (int kc = 0; kc < NKC; kc++) {
        if (kc == NKC - 1) asm volatile("cp.async.wait_group 0;" ::: "memory");
        else               asm volatile("cp.async.wait_group 1;" ::: "memory");
        __syncthreads();

        uint32_t aHb = sb + (kc & 1) * STG;
        uint32_t aLb = aHb + 16384;
        uint32_t bHb = aHb + 32768;
        uint32_t bLb = aHb + 49152;

        int grp = lane >> 3;
        #pragma unroll
        for (int ks = 0; ks < 4; ks++) {
            uint32_t ah[4][4], al[4][4], bh[2][4], bl[2][4];
            #pragma unroll
            for (int mt = 0; mt < 4; mt++) {
                uint32_t off = swz((uint32_t)((wm*64 + mt*16 + (lane & 15)) * 128
                                              + ks*32 + (lane >> 4) * 16));
                ldm_x4(ah[mt], aHb + off);
                ldm_x4(al[mt], aLb + off);
            }
            #pragma unroll
            for (int nt2 = 0; nt2 < 2; nt2++) {
                uint32_t off = swz((uint32_t)((wn*32 + nt2*16 + (grp >> 1)*8 + (lane & 7)) * 128
                                              + ks*32 + (grp & 1) * 16));
                ldm_x4(bh[nt2], bHb + off);
                ldm_x4(bl[nt2], bLb + off);
            }
            #pragma unroll
            for (int mt = 0; mt < 4; mt++)
                #pragma unroll
                for (int nt = 0; nt < 4; nt++) {
                    const uint32_t* bhf = &bh[nt >> 1][(nt & 1) * 2];
                    const uint32_t* blf = &bl[nt >> 1][(nt & 1) * 2];
                    mma16816(acc[mt][nt], ah[mt], bhf);
                    mma16816(acc[mt][nt], ah[mt], blf);
                    mma16816(acc[mt][nt], al[mt], bhf);
                }
        }
        if (kc + 2 < NKC) {
            __syncthreads();
            load_chunk(kc + 2, kc & 1);
        }
    }

    // ---- epilogue ----
    #pragma unroll
    for (int mt = 0; mt < 4; mt++) {
        int row0 = m0 + wm*64 + mt*16 + (lane >> 2);
        #pragma unroll
        for (int nt = 0; nt < 4; nt++) {
            int col = n0 + wn*32 + nt*8 + (lane & 3) * 2;
            float2 bi = *(const float2*)&bias[col];
            size_t o0 = (size_t)row0 * DD + col;
            size_t o1 = (size_t)(row0 + 8) * DD + col;
            float2 v0 = make_float2(acc[mt][nt][0] + bi.x, acc[mt][nt][1] + bi.y);
            float2 v1 = make_float2(acc[mt][nt][2] + bi.x, acc[mt][nt][3] + bi.y);
            if (resid) {
                float2 r0 = *(const float2*)(resid + o0);
                float2 r1 = *(const float2*)(resid + o1);
                v0.x += r0.x; v0.y += r0.y;
                v1.x += r1.x; v1.y += r1.y;
            }
            *(float2*)(C + o0) = v0;
            *(float2*)(C + o1) = v1;
        }
    }
}

// ---------- 1024-point Stockham complex FFT, 512 threads ----------
__device__ __forceinline__ void fft1024(float2* s0, float2* s1, int tid, bool inverse) {
    float2* src = s0;
    float2* dst = s1;
    #pragma unroll
    for (int m = 1; m <= 512; m <<= 1) {
        int jm = tid & ~(m - 1);
        float2 u = src[tid];
        float2 v = src[tid + 512];
        float2 w = g_twid[jm];
        float wy = inverse ? -w.y : w.y;
        float2 sum = make_float2(u.x + v.x, u.y + v.y);
        float2 dif = make_float2(u.x - v.x, u.y - v.y);
        float2 dw  = make_float2(dif.x*w.x - dif.y*wy, dif.x*wy + dif.y*w.x);
        dst[tid + jm]     = sum;
        dst[tid + jm + m] = dw;
        __syncthreads();
        float2* tp = src; src = dst; dst = tp;
    }
}

// ---------- per-token: normalize key, FFT key & value, store Kf and P ----------
__global__ void __launch_bounds__(512) fwd_kernel() {
    __shared__ float2 s0[1024];
    __shared__ float2 s1[1024];
    __shared__ float red[16];
    int t = blockIdx.x, tid = threadIdx.x;

    const float* kr = g_keys + (size_t)t * DD;
    float k0 = kr[tid], k1 = kr[tid + 512];
    float ss = k0*k0 + k1*k1;
    #pragma unroll
    for (int o = 16; o; o >>= 1) ss += __shfl_xor_sync(0xffffffffu, ss, o);
    if ((tid & 31) == 0) red[tid >> 5] = ss;
    __syncthreads();
    if (tid < 16) {
        float v = red[tid];
        #pragma unroll
        for (int o = 8; o; o >>= 1) v += __shfl_xor_sync(0xffffu, v, o);
        if (tid == 0) red[0] = v;
    }
    __syncthreads();
    float scl = 1.0f / fmaxf(sqrtf(red[0]), 1e-12f);

    s0[tid]       = make_float2(k0 * scl, 0.f);
    s0[tid + 512] = make_float2(k1 * scl, 0.f);
    __syncthreads();
    fft1024(s0, s1, tid, false);

    float2 kfa = s0[tid];
    float2 kf512 = make_float2(0.f, 0.f);
    if (tid == 0) kf512 = s0[512];
    g_Kf[(size_t)t * FS + tid] = kfa;
    if (tid == 0) g_Kf[(size_t)t * FS + 512] = kf512;
    __syncthreads();

    const float* vr = g_vals + (size_t)t * DD;
    s0[tid]       = make_float2(vr[tid], 0.f);
    s0[tid + 512] = make_float2(vr[tid + 512], 0.f);
    __syncthreads();
    fft1024(s0, s1, tid, false);

    g_P[(size_t)t * FS + tid] = cmul(kfa, s0[tid]);
    if (tid == 0) g_P[(size_t)t * FS + 512] = cmul(kf512, s0[512]);
}

// ---------- blocked scan pass 1 ----------
__global__ void __launch_bounds__(256) scan1() {
    int idx = blockIdx.x * blockDim.x + threadIdx.x;
    int comp  = idx % COMPS;
    int rest  = idx / COMPS;
    int chunk = rest % NCH;
    int b     = rest / NCH;
    float* Pf = (float*)g_P;
    size_t base = (size_t)(b * LL + chunk * CHL) * (FS * 2) + comp;
    float acc = 0.f;
    #pragma unroll 4
    for (int s = 0; s < CHL; s++) {
        acc += Pf[base];
        Pf[base] = acc;
        base += FS * 2;
    }
    g_aux[(b * NCH + chunk) * COMPS + comp] = acc;
}

// ---------- scan pass 2 ----------
__global__ void __launch_bounds__(256) scan2() {
    int idx = blockIdx.x * blockDim.x + threadIdx.x;
    int comp  = idx % COMPS;
    int rest  = idx / COMPS;
    int chunk = rest % NCH;
    int b     = rest / NCH;
    if (chunk == 0) return;
    float off = 0.f;
    for (int c = 0; c < chunk; c++) off += g_aux[(b * NCH + c) * COMPS + comp];
    float* Pf = (float*)g_P;
    size_t base = (size_t)(b * LL + chunk * CHL) * (FS * 2) + comp;
    #pragma unroll 4
    for (int s = 0; s < CHL; s++) {
        Pf[base] += off;
        base += FS * 2;
    }
}

// ---------- unbind + iFFT + LayerNorm -> bf16 hi/lo ----------
__global__ void __launch_bounds__(512) inv_kernel(const float* __restrict__ ln_g,
                                                  const float* __restrict__ ln_b) {
    __shared__ float2 s0[1024];
    __shared__ float2 s1[1024];
    __shared__ float red[32];
    int t = blockIdx.x, tid = threadIdx.x;
    size_t fb = (size_t)t * FS;

    float2 kf = g_Kf[fb + tid];
    float2 mp = g_P[fb + tid];
    float2 S = make_float2(mp.x*kf.x + mp.y*kf.y, mp.y*kf.x - mp.x*kf.y);
    s0[tid] = S;
    if (tid) {
        s0[1024 - tid] = make_float2(S.x, -S.y);
    } else {
        float2 kf5 = g_Kf[fb + 512];
        float2 mp5 = g_P[fb + 512];
        s0[512] = make_float2(mp5.x*kf5.x + mp5.y*kf5.y, mp5.y*kf5.x - mp5.x*kf5.y);
    }
    __syncthreads();
    fft1024(s0, s1, tid, true);

    int pos = (t & (LL - 1)) + 1;
    float scale = rsqrtf((float)pos) * (1.0f / 1024.0f);
    float r0 = s0[tid].x * scale;
    float r1 = s0[tid + 512].x * scale;

    float sm = r0 + r1;
    float sq = r0*r0 + r1*r1;
    #pragma unroll
    for (int o = 16; o; o >>= 1) {
        sm += __shfl_xor_sync(0xffffffffu, sm, o);
        sq += __shfl_xor_sync(0xffffffffu, sq, o);
    }
    if ((tid & 31) == 0) { red[tid >> 5] = sm; red[16 + (tid >> 5)] = sq; }
    __syncthreads();
    if (tid < 16) {
        float a = red[tid], q = red[16 + tid];
        #pragma unroll
        for (int o = 8; o; o >>= 1) {
            a += __shfl_xor_sync(0xffffu, a, o);
            q += __shfl_xor_sync(0xffffu, q, o);
        }
        if (tid == 0) { red[0] = a; red[16] = q; }
    }
    __syncthreads();
    float mu  = red[0] * (1.0f / 1024.0f);
    float var = red[16] * (1.0f / 1024.0f) - mu * mu;
    float rstd = rsqrtf(var + 1e-5f);

    size_t ob = (size_t)t * DD;
    float y0 = (r0 - mu) * rstd * ln_g[tid]       + ln_b[tid];
    float y1 = (r1 - mu) * rstd * ln_g[tid + 512] + ln_b[tid + 512];
    __nv_bfloat16 h0 = __float2bfloat16_rn(y0);
    __nv_bfloat16 h1 = __float2bfloat16_rn(y1);
    g_rh[ob + tid]       = h0;
    g_rh[ob + tid + 512] = h1;
    g_rl[ob + tid]       = __float2bfloat16_rn(y0 - __bfloat162float(h0));
    g_rl[ob + tid + 512] = __float2bfloat16_rn(y1 - __bfloat162float(h1));
}

// ---------- launch ----------
extern "C" void kernel_launch(void* const* d_in, const int* in_sizes, int n_in,
                              void* d_out, int out_size) {
    const float* x    = (const float*)d_in[0];
    const float* Wk   = (const float*)d_in[1];
    const float* bk   = (const float*)d_in[2];
    const float* Wv   = (const float*)d_in[3];
    const float* bv   = (const float*)d_in[4];
    const float* ln_g = (const float*)d_in[5];
    const float* ln_b = (const float*)d_in[6];
    const float* Wo   = (const float*)d_in[7];
    const float* bo   = (const float*)d_in[8];
    float* out = (float*)d_out;

    float *keys, *vals;
    __nv_bfloat16 *xh, *xl, *rh, *rl, *wkh, *wkl, *wvh, *wvl, *woh, *wol;
    cudaGetSymbolAddress((void**)&keys, g_keys);
    cudaGetSymbolAddress((void**)&vals, g_vals);
    cudaGetSymbolAddress((void**)&xh, g_xh);   cudaGetSymbolAddress((void**)&xl, g_xl);
    cudaGetSymbolAddress((void**)&rh, g_rh);   cudaGetSymbolAddress((void**)&rl, g_rl);
    cudaGetSymbolAddress((void**)&wkh, g_Wkh); cudaGetSymbolAddress((void**)&wkl, g_Wkl);
    cudaGetSymbolAddress((void**)&wvh, g_Wvh); cudaGetSymbolAddress((void**)&wvl, g_Wvl);
    cudaGetSymbolAddress((void**)&woh, g_Woh); cudaGetSymbolAddress((void**)&wol, g_Wol);

    cudaFuncSetAttribute(gemm_bf16, cudaFuncAttributeMaxDynamicSharedMemorySize, GEMM_SMEM);

    init_twid<<<1, 512>>>();

    conv_split<<<(NT*DD/4 + 255)/256, 256>>>(x,  xh,  xl,  NT*DD/4);
    conv_split<<<(DD*DD/4 + 255)/256, 256>>>(Wk, wkh, wkl, DD*DD/4);
    conv_split<<<(DD*DD/4 + 255)/256, 256>>>(Wv, wvh, wvl, DD*DD/4);
    conv_split<<<(DD*DD/4 + 255)/256, 256>>>(Wo, woh, wol, DD*DD/4);

    dim3 gg(TN == 128 ? 8 : 8, NT / TM);  // (8, 128)
    gemm_bf16<<<gg, 256, GEMM_SMEM>>>(xh, xl, wkh, wkl, bk, nullptr, keys);
    gemm_bf16<<<gg, 256, GEMM_SMEM>>>(xh, xl, wvh, wvl, bv, nullptr, vals);

    fwd_kernel<<<NT, 512>>>();

    scan1<<<(BB * NCH * COMPS) / 256, 256>>>();
    scan2<<<(BB * NCH * COMPS) / 256, 256>>>();

    inv_kernel<<<NT, 512>>>(ln_g, ln_b);

    gemm_bf16<<<gg, 256, GEMM_SMEM>>>(rh, rl, woh, wol, bo, x, out);
}

// round 6
// speedup vs baseline: 3.1235x; 1.1587x over previous
#include <cuda_runtime.h>
#include <cuda_bf16.h>
#include <math.h>
#include <stdint.h>

#define BB 4
#define LL 4096
#define DD 1024
#define NT (BB*LL)          // 16384 tokens
#define NF 513
#define FS 520
#define NCH 64
#define CHL (LL/NCH)
#define COMPS (NF*2)

// GEMM tiling
#define TM 128
#define TN 128
#define KC 64
#define NKC (DD/KC)         // 16
#define STG 65536
#define GEMM_SMEM (2*STG)   // 128KB

// ---------- scratch ----------
__device__ float  g_keys[NT*DD];
__device__ float  g_vals[NT*DD];
__device__ float2 g_Kf[NT*FS];
__device__ float2 g_P [NT*FS];
__device__ float  g_aux[BB*NCH*COMPS];
__device__ float2 g_twid[512];
__device__ __align__(16) __nv_bfloat16 g_xh[NT*DD],  g_xl[NT*DD];
__device__ __align__(16) __nv_bfloat16 g_rh[NT*DD],  g_rl[NT*DD];
__device__ __align__(16) __nv_bfloat16 g_Wkh[DD*DD], g_Wkl[DD*DD];
__device__ __align__(16) __nv_bfloat16 g_Wvh[DD*DD], g_Wvl[DD*DD];
__device__ __align__(16) __nv_bfloat16 g_Woh[DD*DD], g_Wol[DD*DD];

// ---------- helpers ----------
__device__ __forceinline__ uint32_t smem_u32(const void* p) {
    uint32_t a;
    asm("{ .reg .u64 t; cvta.to.shared.u64 t, %1; cvt.u32.u64 %0, t; }" : "=r"(a) : "l"(p));
    return a;
}
__device__ __forceinline__ uint32_t swz(uint32_t off) {
    return off ^ ((off >> 3) & 0x70);
}
__device__ __forceinline__ void ldm_x4(uint32_t* r, uint32_t addr) {
    asm volatile("ldmatrix.sync.aligned.m8n8.x4.shared.b16 {%0,%1,%2,%3}, [%4];"
        : "=r"(r[0]), "=r"(r[1]), "=r"(r[2]), "=r"(r[3]) : "r"(addr));
}
__device__ __forceinline__ void mma16816(float* d, const uint32_t* a, const uint32_t* b) {
    asm volatile("mma.sync.aligned.m16n8k16.row.col.f32.bf16.bf16.f32 "
        "{%0,%1,%2,%3}, {%4,%5,%6,%7}, {%8,%9}, {%0,%1,%2,%3};"
        : "+f"(d[0]), "+f"(d[1]), "+f"(d[2]), "+f"(d[3])
        : "r"(a[0]), "r"(a[1]), "r"(a[2]), "r"(a[3]), "r"(b[0]), "r"(b[1]));
}
__device__ __forceinline__ void cp16(uint32_t dst, const void* src) {
    asm volatile("cp.async.cg.shared.global [%0], [%1], 16;" :: "r"(dst), "l"(src));
}

// ---------- twiddles ----------
__global__ void init_twid() {
    int t = threadIdx.x;
    double a = -2.0 * M_PI * (double)t / 1024.0;
    g_twid[t] = make_float2((float)cos(a), (float)sin(a));
}

__device__ __forceinline__ float2 cmul(float2 a, float2 b) {
    return make_float2(a.x*b.x - a.y*b.y, a.x*b.y + a.y*b.x);
}

// ---------- generic Stockham FFT (2*NH points, NH lanes, twiddle stride TS) ----------
// tid in [0, NH). Returns pointer to result buffer. ALL block threads must call
// (same trip count) because of __syncthreads inside.
template<int NH, int TS>
__device__ __forceinline__ float2* fftT(float2* s0, float2* s1, int tid, bool inverse) {
    float2* src = s0;
    float2* dst = s1;
    #pragma unroll
    for (int m = 1; m <= NH; m <<= 1) {
        int jm = tid & ~(m - 1);
        float2 u = src[tid];
        float2 v = src[tid + NH];
        float2 w = g_twid[jm * TS];
        float wy = inverse ? -w.y : w.y;
        float2 sum = make_float2(u.x + v.x, u.y + v.y);
        float2 dif = make_float2(u.x - v.x, u.y - v.y);
        float2 dw  = make_float2(dif.x*w.x - dif.y*wy, dif.x*wy + dif.y*w.x);
        dst[tid + jm]     = sum;
        dst[tid + jm + m] = dw;
        __syncthreads();
        float2* tp = src; src = dst; dst = tp;
    }
    return src;
}

// ---------- fp32 -> bf16 hi/lo split ----------
__global__ void __launch_bounds__(256) conv_split(const float* __restrict__ src,
                                                  __nv_bfloat16* __restrict__ hi,
                                                  __nv_bfloat16* __restrict__ lo, int n4) {
    int i = blockIdx.x * blockDim.x + threadIdx.x;
    if (i >= n4) return;
    float4 v = ((const float4*)src)[i];
    __nv_bfloat16 h0 = __float2bfloat16_rn(v.x), h1 = __float2bfloat16_rn(v.y);
    __nv_bfloat16 h2 = __float2bfloat16_rn(v.z), h3 = __float2bfloat16_rn(v.w);
    __nv_bfloat16 l0 = __float2bfloat16_rn(v.x - __bfloat162float(h0));
    __nv_bfloat16 l1 = __float2bfloat16_rn(v.y - __bfloat162float(h1));
    __nv_bfloat16 l2 = __float2bfloat16_rn(v.z - __bfloat162float(h2));
    __nv_bfloat16 l3 = __float2bfloat16_rn(v.w - __bfloat162float(h3));
    __nv_bfloat162* H = (__nv_bfloat162*)hi;
    __nv_bfloat162* L = (__nv_bfloat162*)lo;
    H[i*2]   = __nv_bfloat162(h0, h1);
    H[i*2+1] = __nv_bfloat162(h2, h3);
    L[i*2]   = __nv_bfloat162(l0, l1);
    L[i*2+1] = __nv_bfloat162(l2, l3);
}

// ---------- HMMA bf16-split GEMM ----------
__global__ void __launch_bounds__(256, 1) gemm_bf16(
    const __nv_bfloat16* __restrict__ Ah, const __nv_bfloat16* __restrict__ Al,
    const __nv_bfloat16* __restrict__ Bh, const __nv_bfloat16* __restrict__ Bl,
    const float* __restrict__ bias, const float* __restrict__ resid,
    float* __restrict__ C)
{
    extern __shared__ char smem[];
    uint32_t sb = smem_u32(smem);
    int tid = threadIdx.x, lane = tid & 31, wid = tid >> 5;
    int wm = wid >> 2, wn = wid & 3;
    int m0 = blockIdx.y * TM, n0 = blockIdx.x * TN;

    const __nv_bfloat16* srcs[4] = {Ah, Al, Bh, Bl};
    const int rb[4] = {m0, m0, n0, n0};

    float acc[4][4][4];
    #pragma unroll
    for (int i = 0; i < 4; i++)
        #pragma unroll
        for (int j = 0; j < 4; j++)
            #pragma unroll
            for (int k = 0; k < 4; k++) acc[i][j][k] = 0.f;

    auto load_chunk = [&](int kc, int st) {
        #pragma unroll
        for (int i = 0; i < 4; i++) {
            int ch = tid + i * 256;
            int row = ch >> 3, j = ch & 7;
            uint32_t swo = swz((uint32_t)(row * 128 + j * 16));
            #pragma unroll
            for (int bu = 0; bu < 4; bu++) {
                const void* g = srcs[bu] + (size_t)(rb[bu] + row) * DD + kc * KC + j * 8;
                cp16(sb + st * STG + bu * 16384 + swo, g);
            }
        }
        asm volatile("cp.async.commit_group;" ::: "memory");
    };

    load_chunk(0, 0);
    load_chunk(1, 1);

    for (int kc = 0; kc < NKC; kc++) {
        if (kc == NKC - 1) asm volatile("cp.async.wait_group 0;" ::: "memory");
        else               asm volatile("cp.async.wait_group 1;" ::: "memory");
        __syncthreads();

        uint32_t aHb = sb + (kc & 1) * STG;
        uint32_t aLb = aHb + 16384;
        uint32_t bHb = aHb + 32768;
        uint32_t bLb = aHb + 49152;

        int grp = lane >> 3;
        #pragma unroll
        for (int ks = 0; ks < 4; ks++) {
            uint32_t ah[4][4], al[4][4], bh[2][4], bl[2][4];
            #pragma unroll
            for (int mt = 0; mt < 4; mt++) {
                uint32_t off = swz((uint32_t)((wm*64 + mt*16 + (lane & 15)) * 128
                                              + ks*32 + (lane >> 4) * 16));
                ldm_x4(ah[mt], aHb + off);
                ldm_x4(al[mt], aLb + off);
            }
            #pragma unroll
            for (int nt2 = 0; nt2 < 2; nt2++) {
                uint32_t off = swz((uint32_t)((wn*32 + nt2*16 + (grp >> 1)*8 + (lane & 7)) * 128
                                              + ks*32 + (grp & 1) * 16));
                ldm_x4(bh[nt2], bHb + off);
                ldm_x4(bl[nt2], bLb + off);
            }
            #pragma unroll
            for (int mt = 0; mt < 4; mt++)
                #pragma unroll
                for (int nt = 0; nt < 4; nt++) {
                    const uint32_t* bhf = &bh[nt >> 1][(nt & 1) * 2];
                    const uint32_t* blf = &bl[nt >> 1][(nt & 1) * 2];
                    mma16816(acc[mt][nt], ah[mt], bhf);
                    mma16816(acc[mt][nt], ah[mt], blf);
                    mma16816(acc[mt][nt], al[mt], bhf);
                }
        }
        if (kc + 2 < NKC) {
            __syncthreads();
            load_chunk(kc + 2, kc & 1);
        }
    }

    #pragma unroll
    for (int mt = 0; mt < 4; mt++) {
        int row0 = m0 + wm*64 + mt*16 + (lane >> 2);
        #pragma unroll
        for (int nt = 0; nt < 4; nt++) {
            int col = n0 + wn*32 + nt*8 + (lane & 3) * 2;
            float2 bi = *(const float2*)&bias[col];
            size_t o0 = (size_t)row0 * DD + col;
            size_t o1 = (size_t)(row0 + 8) * DD + col;
            float2 v0 = make_float2(acc[mt][nt][0] + bi.x, acc[mt][nt][1] + bi.y);
            float2 v1 = make_float2(acc[mt][nt][2] + bi.x, acc[mt][nt][3] + bi.y);
            if (resid) {
                float2 r0 = *(const float2*)(resid + o0);
                float2 r1 = *(const float2*)(resid + o1);
                v0.x += r0.x; v0.y += r0.y;
                v1.x += r1.x; v1.y += r1.y;
            }
            *(float2*)(C + o0) = v0;
            *(float2*)(C + o1) = v1;
        }
    }
}

// ---------- fwd: pack k+iv, ONE 1024-pt FFT, unpack Kf/Vf, store Kf & P ----------
__global__ void __launch_bounds__(512) fwd_kernel() {
    __shared__ float2 s0[1024];
    __shared__ float2 s1[1024];
    __shared__ float red[16];
    int t = blockIdx.x, tid = threadIdx.x;

    const float* kr = g_keys + (size_t)t * DD;
    const float* vr = g_vals + (size_t)t * DD;
    float k0 = kr[tid], k1 = kr[tid + 512];
    float v0 = vr[tid], v1 = vr[tid + 512];

    float ss = k0*k0 + k1*k1;
    #pragma unroll
    for (int o = 16; o; o >>= 1) ss += __shfl_xor_sync(0xffffffffu, ss, o);
    if ((tid & 31) == 0) red[tid >> 5] = ss;
    __syncthreads();
    if (tid < 16) {
        float v = red[tid];
        #pragma unroll
        for (int o = 8; o; o >>= 1) v += __shfl_xor_sync(0xffffu, v, o);
        if (tid == 0) red[0] = v;
    }
    __syncthreads();
    float scl = 1.0f / fmaxf(sqrtf(red[0]), 1e-12f);

    // z = k_norm + i*v
    s0[tid]       = make_float2(k0 * scl, v0);
    s0[tid + 512] = make_float2(k1 * scl, v1);
    __syncthreads();
    float2* Z = fftT<512, 1>(s0, s1, tid, false);

    float2 za = Z[tid];
    float2 zb = Z[(1024 - tid) & 1023];
    // Kf = (za + conj(zb))/2 ; Vf = -i(za - conj(zb))/2
    float2 Kf = make_float2(0.5f * (za.x + zb.x), 0.5f * (za.y - zb.y));
    float2 dv = make_float2(za.x - zb.x, za.y + zb.y);
    float2 Vf = make_float2(0.5f * dv.y, -0.5f * dv.x);

    size_t fb = (size_t)t * FS;
    g_Kf[fb + tid] = Kf;
    g_P [fb + tid] = cmul(Kf, Vf);
    if (tid == 0) {
        float2 z5 = Z[512];
        float2 Kf5 = make_float2(z5.x, 0.f);
        float2 Vf5 = make_float2(z5.y, 0.f);
        g_Kf[fb + 512] = Kf5;
        g_P [fb + 512] = cmul(Kf5, Vf5);
    }
}

// ---------- blocked scan pass 1 ----------
__global__ void __launch_bounds__(256) scan1() {
    int idx = blockIdx.x * blockDim.x + threadIdx.x;
    int comp  = idx % COMPS;
    int rest  = idx / COMPS;
    int chunk = rest % NCH;
    int b     = rest / NCH;
    float* Pf = (float*)g_P;
    size_t base = (size_t)(b * LL + chunk * CHL) * (FS * 2) + comp;
    float acc = 0.f;
    #pragma unroll 4
    for (int s = 0; s < CHL; s++) {
        acc += Pf[base];
        Pf[base] = acc;
        base += FS * 2;
    }
    g_aux[(b * NCH + chunk) * COMPS + comp] = acc;
}

// ---------- scan pass 2 ----------
__global__ void __launch_bounds__(256) scan2() {
    int idx = blockIdx.x * blockDim.x + threadIdx.x;
    int comp  = idx % COMPS;
    int rest  = idx / COMPS;
    int chunk = rest % NCH;
    int b     = rest / NCH;
    if (chunk == 0) return;
    float off = 0.f;
    for (int c = 0; c < chunk; c++) off += g_aux[(b * NCH + c) * COMPS + comp];
    float* Pf = (float*)g_P;
    size_t base = (size_t)(b * LL + chunk * CHL) * (FS * 2) + comp;
    #pragma unroll 4
    for (int s = 0; s < CHL; s++) {
        Pf[base] += off;
        base += FS * 2;
    }
}

// ---------- inv: unbind, 512-pt packed irfft, LayerNorm -> bf16 hi/lo ----------
// 2 tokens per block: half = tid/256 handles token blockIdx.x*2 + half.
__global__ void __launch_bounds__(512) inv_kernel(const float* __restrict__ ln_g,
                                                  const float* __restrict__ ln_b) {
    __shared__ float2 sS[2][516];        // S bins 0..512 per half
    __shared__ float2 s0[2][512];
    __shared__ float2 s1[2][512];
    __shared__ float red[2][16];
    int tid = threadIdx.x;
    int half = tid >> 8, htid = tid & 255;
    int t = blockIdx.x * 2 + half;
    size_t fb = (size_t)t * FS;

    // S[k] = cumP[k] * conj(Kf[k]) for k = htid, htid+256, (and 512 via htid==0)
    #pragma unroll
    for (int q = 0; q < 2; q++) {
        int k = htid + q * 256;
        float2 kf = g_Kf[fb + k];
        float2 mp = g_P[fb + k];
        sS[half][k] = make_float2(mp.x*kf.x + mp.y*kf.y, mp.y*kf.x - mp.x*kf.y);
    }
    if (htid == 0) {
        float2 kf = g_Kf[fb + 512];
        float2 mp = g_P[fb + 512];
        sS[half][512] = make_float2(mp.x*kf.x + mp.y*kf.y, mp.y*kf.x - mp.x*kf.y);
    }
    __syncthreads();

    // Zf[k] = (S[k]+conj(S[512-k]))/2 + i*(S[k]-conj(S[512-k]))/2 * e^{+2pi i k/1024}
    {
        int k = htid;
        float2 Sa = sS[half][k];
        float2 Sb = sS[half][512 - k];
        float2 tw = g_twid[k];            // e^{-2pi i k/1024}; need conj
        float twx = tw.x, twy = -tw.y;
        float2 Xe = make_float2(0.5f*(Sa.x + Sb.x), 0.5f*(Sa.y - Sb.y));
        float2 Xd = make_float2(0.5f*(Sa.x - Sb.x), 0.5f*(Sa.y + Sb.y));
        float2 Xo = make_float2(Xd.x*twx - Xd.y*twy, Xd.x*twy + Xd.y*twx);
        s0[half][k] = make_float2(Xe.x - Xo.y, Xe.y + Xo.x);   // Xe + i*Xo
        if (k > 0) {
            int k2 = 512 - k;
            float2 tw2 = g_twid[k2];
            float t2x = tw2.x, t2y = -tw2.y;
            // swap roles: Zf[k2] uses S[k2]=Sb, conj(S[512-k2]=Sa)
            float2 Xe2 = make_float2(0.5f*(Sb.x + Sa.x), 0.5f*(Sb.y - Sa.y));
            float2 Xd2 = make_float2(0.5f*(Sb.x - Sa.x), 0.5f*(Sb.y + Sa.y));
            float2 Xo2 = make_float2(Xd2.x*t2x - Xd2.y*t2y, Xd2.x*t2y + Xd2.y*t2x);
            s0[half][k2] = make_float2(Xe2.x - Xo2.y, Xe2.y + Xo2.x);
        } else {
            // k = 256 (self-paired)
            float2 Sc = sS[half][256];
            float2 tw2 = g_twid[256];
            float t2x = tw2.x, t2y = -tw2.y;
            float2 Xe2 = make_float2(Sc.x, 0.f);
            float2 Xd2 = make_float2(0.f, Sc.y);
            float2 Xo2 = make_float2(Xd2.x*t2x - Xd2.y*t2y, Xd2.x*t2y + Xd2.y*t2x);
            s0[half][256] = make_float2(Xe2.x - Xo2.y, Xe2.y + Xo2.x);
        }
    }
    __syncthreads();

    float2* Zr = fftT<256, 2>(s0[half], s1[half], htid, true);   // 9 stages

    int pos = (t & (LL - 1)) + 1;
    float scale = rsqrtf((float)pos) * (1.0f / 512.0f);
    float2 zA = Zr[htid];         // x[2*htid], x[2*htid+1]
    float2 zB = Zr[htid + 256];   // x[2*htid+512], x[2*htid+513]
    float r0 = zA.x * scale, r1 = zA.y * scale;
    float r2 = zB.x * scale, r3 = zB.y * scale;

    float sm = r0 + r1 + r2 + r3;
    float sq = r0*r0 + r1*r1 + r2*r2 + r3*r3;
    #pragma unroll
    for (int o = 16; o; o >>= 1) {
        sm += __shfl_xor_sync(0xffffffffu, sm, o);
        sq += __shfl_xor_sync(0xffffffffu, sq, o);
    }
    int w8 = (tid >> 5) & 7;
    if ((tid & 31) == 0) { red[half][w8] = sm; red[half][8 + w8] = sq; }
    __syncthreads();
    float smT = 0.f, sqT = 0.f;
    #pragma unroll
    for (int i = 0; i < 8; i++) { smT += red[half][i]; sqT += red[half][8 + i]; }
    float mu  = smT * (1.0f / 1024.0f);
    float var = sqT * (1.0f / 1024.0f) - mu * mu;
    float rstd = rsqrtf(var + 1e-5f);

    int n0 = 2 * htid, n1 = 2 * htid + 512;
    float2 gA = *(const float2*)&ln_g[n0];
    float2 bA = *(const float2*)&ln_b[n0];
    float2 gB = *(const float2*)&ln_g[n1];
    float2 bB = *(const float2*)&ln_b[n1];
    float y0 = (r0 - mu) * rstd * gA.x + bA.x;
    float y1 = (r1 - mu) * rstd * gA.y + bA.y;
    float y2 = (r2 - mu) * rstd * gB.x + bB.x;
    float y3 = (r3 - mu) * rstd * gB.y + bB.y;

    __nv_bfloat16 h0 = __float2bfloat16_rn(y0), h1 = __float2bfloat16_rn(y1);
    __nv_bfloat16 h2 = __float2bfloat16_rn(y2), h3 = __float2bfloat16_rn(y3);
    __nv_bfloat162* RH = (__nv_bfloat162*)g_rh;
    __nv_bfloat162* RL = (__nv_bfloat162*)g_rl;
    size_t hb = (size_t)t * 512;
    RH[hb + htid]       = __nv_bfloat162(h0, h1);
    RH[hb + 256 + htid] = __nv_bfloat162(h2, h3);
    RL[hb + htid]       = __nv_bfloat162(__float2bfloat16_rn(y0 - __bfloat162float(h0)),
                                         __float2bfloat16_rn(y1 - __bfloat162float(h1)));
    RL[hb + 256 + htid] = __nv_bfloat162(__float2bfloat16_rn(y2 - __bfloat162float(h2)),
                                         __float2bfloat16_rn(y3 - __bfloat162float(h3)));
}

// ---------- launch ----------
extern "C" void kernel_launch(void* const* d_in, const int* in_sizes, int n_in,
                              void* d_out, int out_size) {
    const float* x    = (const float*)d_in[0];
    const float* Wk   = (const float*)d_in[1];
    const float* bk   = (const float*)d_in[2];
    const float* Wv   = (const float*)d_in[3];
    const float* bv   = (const float*)d_in[4];
    const float* ln_g = (const float*)d_in[5];
    const float* ln_b = (const float*)d_in[6];
    const float* Wo   = (const float*)d_in[7];
    const float* bo   = (const float*)d_in[8];
    float* out = (float*)d_out;

    float *keys, *vals;
    __nv_bfloat16 *xh, *xl, *rh, *rl, *wkh, *wkl, *wvh, *wvl, *woh, *wol;
    cudaGetSymbolAddress((void**)&keys, g_keys);
    cudaGetSymbolAddress((void**)&vals, g_vals);
    cudaGetSymbolAddress((void**)&xh, g_xh);   cudaGetSymbolAddress((void**)&xl, g_xl);
    cudaGetSymbolAddress((void**)&rh, g_rh);   cudaGetSymbolAddress((void**)&rl, g_rl);
    cudaGetSymbolAddress((void**)&wkh, g_Wkh); cudaGetSymbolAddress((void**)&wkl, g_Wkl);
    cudaGetSymbolAddress((void**)&wvh, g_Wvh); cudaGetSymbolAddress((void**)&wvl, g_Wvl);
    cudaGetSymbolAddress((void**)&woh, g_Woh); cudaGetSymbolAddress((void**)&wol, g_Wol);

    cudaFuncSetAttribute(gemm_bf16, cudaFuncAttributeMaxDynamicSharedMemorySize, GEMM_SMEM);

    init_twid<<<1, 512>>>();

    conv_split<<<(NT*DD/4 + 255)/256, 256>>>(x,  xh,  xl,  NT*DD/4);
    conv_split<<<(DD*DD/4 + 255)/256, 256>>>(Wk, wkh, wkl, DD*DD/4);
    conv_split<<<(DD*DD/4 + 255)/256, 256>>>(Wv, wvh, wvl, DD*DD/4);
    conv_split<<<(DD*DD/4 + 255)/256, 256>>>(Wo, woh, wol, DD*DD/4);

    dim3 gg(8, NT / TM);  // (8, 128)
    gemm_bf16<<<gg, 256, GEMM_SMEM>>>(xh, xl, wkh, wkl, bk, nullptr, keys);
    gemm_bf16<<<gg, 256, GEMM_SMEM>>>(xh, xl, wvh, wvl, bv, nullptr, vals);

    fwd_kernel<<<NT, 512>>>();

    scan1<<<(BB * NCH * COMPS) / 256, 256>>>();
    scan2<<<(BB * NCH * COMPS) / 256, 256>>>();

    inv_kernel<<<NT/2, 512>>>(ln_g, ln_b);

    gemm_bf16<<<gg, 256, GEMM_SMEM>>>(rh, rl, woh, wol, bo, x, out);
}

// round 7
// speedup vs baseline: 3.2622x; 1.0444x over previous
#include <cuda_runtime.h>
#include <cuda_bf16.h>
#include <math.h>
#include <stdint.h>

#define BB 4
#define LL 4096
#define DD 1024
#define NT (BB*LL)          // 16384 tokens
#define NF 513
#define FS 520
#define NCH 64
#define CHL (LL/NCH)
#define COMPS (NF*2)

// GEMM tiling
#define TM 128
#define TN 128
#define KC 64
#define NKC (DD/KC)         // 16
#define STG 65536
#define GEMM_SMEM (2*STG)   // 128KB

// ---------- scratch ----------
__device__ float  g_keys[NT*DD];
__device__ float  g_vals[NT*DD];
__device__ float2 g_Kf[NT*FS];
__device__ float2 g_P [NT*FS];
__device__ float  g_aux[BB*NCH*COMPS];
__device__ float2 g_twid[512];
__device__ __align__(16) __nv_bfloat16 g_xh[NT*DD],  g_xl[NT*DD];
__device__ __align__(16) __nv_bfloat16 g_rh[NT*DD],  g_rl[NT*DD];
__device__ __align__(16) __nv_bfloat16 g_Wkh[DD*DD], g_Wkl[DD*DD];
__device__ __align__(16) __nv_bfloat16 g_Wvh[DD*DD], g_Wvl[DD*DD];
__device__ __align__(16) __nv_bfloat16 g_Woh[DD*DD], g_Wol[DD*DD];

// ---------- helpers ----------
__device__ __forceinline__ uint32_t smem_u32(const void* p) {
    uint32_t a;
    asm("{ .reg .u64 t; cvta.to.shared.u64 t, %1; cvt.u32.u64 %0, t; }" : "=r"(a) : "l"(p));
    return a;
}
__device__ __forceinline__ uint32_t swz(uint32_t off) {
    return off ^ ((off >> 3) & 0x70);
}
__device__ __forceinline__ void ldm_x4(uint32_t* r, uint32_t addr) {
    asm volatile("ldmatrix.sync.aligned.m8n8.x4.shared.b16 {%0,%1,%2,%3}, [%4];"
        : "=r"(r[0]), "=r"(r[1]), "=r"(r[2]), "=r"(r[3]) : "r"(addr));
}
__device__ __forceinline__ void mma16816(float* d, const uint32_t* a, const uint32_t* b) {
    asm volatile("mma.sync.aligned.m16n8k16.row.col.f32.bf16.bf16.f32 "
        "{%0,%1,%2,%3}, {%4,%5,%6,%7}, {%8,%9}, {%0,%1,%2,%3};"
        : "+f"(d[0]), "+f"(d[1]), "+f"(d[2]), "+f"(d[3])
        : "r"(a[0]), "r"(a[1]), "r"(a[2]), "r"(a[3]), "r"(b[0]), "r"(b[1]));
}
__device__ __forceinline__ void cp16(uint32_t dst, const void* src) {
    asm volatile("cp.async.cg.shared.global [%0], [%1], 16;" :: "r"(dst), "l"(src));
}

// ---------- twiddles ----------
__global__ void init_twid() {
    int t = threadIdx.x;
    double a = -2.0 * M_PI * (double)t / 1024.0;
    g_twid[t] = make_float2((float)cos(a), (float)sin(a));
}

__device__ __forceinline__ float2 cmul(float2 a, float2 b) {
    return make_float2(a.x*b.x - a.y*b.y, a.x*b.y + a.y*b.x);
}
__device__ __forceinline__ float2 cadd(float2 a, float2 b) { return make_float2(a.x+b.x, a.y+b.y); }
__device__ __forceinline__ float2 csub(float2 a, float2 b) { return make_float2(a.x-b.x, a.y-b.y); }
// multiply by twiddle (wx, wy*(inverse?-1:1))
__device__ __forceinline__ float2 cmw(float2 d, float wx, float wy) {
    return make_float2(d.x*wx - d.y*wy, d.x*wy + d.y*wx);
}

// ---------- radix-2^2 Stockham FFT: 2*NH points, NH/2 lanes ----------
// Thread lane j in [0, NH/2). Covers stage pairs (m,2m) for m=1,4,...
// For log2(2NH) even (e.g. 1024 pts) this completes the FFT (returns result buf).
// For odd (512 pts) the caller must do the final twiddle-free radix-2 stage.
template<int NH, int TS>
__device__ __forceinline__ float2* fft_r22(float2* s0, float2* s1, int j, bool inverse) {
    const int NQ = NH / 2;
    float2* src = s0;
    float2* dst = s1;
    #pragma unroll
    for (int m = 1; m <= NQ; m <<= 2) {
        int jm = j & ~(m - 1);
        float2 a = src[j], b = src[j + NQ], c = src[j + NH], d = src[j + NQ + NH];
        float2 w1 = g_twid[jm * TS];
        float2 w2 = g_twid[(jm + NQ) * TS];
        float w1y = inverse ? -w1.y : w1.y;
        float w2y = inverse ? -w2.y : w2.y;
        float2 sv1 = cadd(a, c);
        float2 tv1 = cmw(csub(a, c), w1.x, w1y);
        float2 sv2 = cadd(b, d);
        float2 tv2 = cmw(csub(b, d), w2.x, w2y);
        int p1 = j + jm;
        int p2 = p1 + m;
        int jmA = p1 & ~(2*m - 1);
        int jmB = p2 & ~(2*m - 1);
        float2 wA = g_twid[jmA * TS];
        float2 wB = g_twid[jmB * TS];
        float wAy = inverse ? -wA.y : wA.y;
        float wBy = inverse ? -wB.y : wB.y;
        dst[p1 + jmA]         = cadd(sv1, sv2);
        dst[p1 + jmA + 2*m]   = cmw(csub(sv1, sv2), wA.x, wAy);
        dst[p2 + jmB]         = cadd(tv1, tv2);
        dst[p2 + jmB + 2*m]   = cmw(csub(tv1, tv2), wB.x, wBy);
        __syncthreads();
        float2* tp = src; src = dst; dst = tp;
    }
    return src;
}

// ---------- fp32 -> bf16 hi/lo split ----------
__global__ void __launch_bounds__(256) conv_split(const float* __restrict__ src,
                                                  __nv_bfloat16* __restrict__ hi,
                                                  __nv_bfloat16* __restrict__ lo, int n4) {
    int i = blockIdx.x * blockDim.x + threadIdx.x;
    if (i >= n4) return;
    float4 v = ((const float4*)src)[i];
    __nv_bfloat16 h0 = __float2bfloat16_rn(v.x), h1 = __float2bfloat16_rn(v.y);
    __nv_bfloat16 h2 = __float2bfloat16_rn(v.z), h3 = __float2bfloat16_rn(v.w);
    __nv_bfloat16 l0 = __float2bfloat16_rn(v.x - __bfloat162float(h0));
    __nv_bfloat16 l1 = __float2bfloat16_rn(v.y - __bfloat162float(h1));
    __nv_bfloat16 l2 = __float2bfloat16_rn(v.z - __bfloat162float(h2));
    __nv_bfloat16 l3 = __float2bfloat16_rn(v.w - __bfloat162float(h3));
    __nv_bfloat162* H = (__nv_bfloat162*)hi;
    __nv_bfloat162* L = (__nv_bfloat162*)lo;
    H[i*2]   = __nv_bfloat162(h0, h1);
    H[i*2+1] = __nv_bfloat162(h2, h3);
    L[i*2]   = __nv_bfloat162(l0, l1);
    L[i*2+1] = __nv_bfloat162(l2, l3);
}

// ---------- HMMA bf16-split GEMM ----------
__global__ void __launch_bounds__(256, 1) gemm_bf16(
    const __nv_bfloat16* __restrict__ Ah, const __nv_bfloat16* __restrict__ Al,
    const __nv_bfloat16* __restrict__ Bh, const __nv_bfloat16* __restrict__ Bl,
    const float* __restrict__ bias, const float* __restrict__ resid,
    float* __restrict__ C)
{
    extern __shared__ char smem[];
    uint32_t sb = smem_u32(smem);
    int tid = threadIdx.x, lane = tid & 31, wid = tid >> 5;
    int wm = wid >> 2, wn = wid & 3;
    int m0 = blockIdx.y * TM, n0 = blockIdx.x * TN;

    const __nv_bfloat16* srcs[4] = {Ah, Al, Bh, Bl};
    const int rb[4] = {m0, m0, n0, n0};

    float acc[4][4][4];
    #pragma unroll
    for (int i = 0; i < 4; i++)
        #pragma unroll
        for (int j = 0; j < 4; j++)
            #pragma unroll
            for (int k = 0; k < 4; k++) acc[i][j][k] = 0.f;

    auto load_chunk = [&](int kc, int st) {
        #pragma unroll
        for (int i = 0; i < 4; i++) {
            int ch = tid + i * 256;
            int row = ch >> 3, j = ch & 7;
            uint32_t swo = swz((uint32_t)(row * 128 + j * 16));
            #pragma unroll
            for (int bu = 0; bu < 4; bu++) {
                const void* g = srcs[bu] + (size_t)(rb[bu] + row) * DD + kc * KC + j * 8;
                cp16(sb + st * STG + bu * 16384 + swo, g);
            }
        }
        asm volatile("cp.async.commit_group;" ::: "memory");
    };

    load_chunk(0, 0);
    load_chunk(1, 1);

    for (int kc = 0; kc < NKC; kc++) {
        if (kc == NKC - 1) asm volatile("cp.async.wait_group 0;" ::: "memory");
        else               asm volatile("cp.async.wait_group 1;" ::: "memory");
        __syncthreads();

        uint32_t aHb = sb + (kc & 1) * STG;
        uint32_t aLb = aHb + 16384;
        uint32_t bHb = aHb + 32768;
        uint32_t bLb = aHb + 49152;

        int grp = lane >> 3;
        #pragma unroll
        for (int ks = 0; ks < 4; ks++) {
            uint32_t ah[4][4], al[4][4], bh[2][4], bl[2][4];
            #pragma unroll
            for (int mt = 0; mt < 4; mt++) {
                uint32_t off = swz((uint32_t)((wm*64 + mt*16 + (lane & 15)) * 128
                                              + ks*32 + (lane >> 4) * 16));
                ldm_x4(ah[mt], aHb + off);
                ldm_x4(al[mt], aLb + off);
            }
            #pragma unroll
            for (int nt2 = 0; nt2 < 2; nt2++) {
                uint32_t off = swz((uint32_t)((wn*32 + nt2*16 + (grp >> 1)*8 + (lane & 7)) * 128
                                              + ks*32 + (grp & 1) * 16));
                ldm_x4(bh[nt2], bHb + off);
                ldm_x4(bl[nt2], bLb + off);
            }
            #pragma unroll
            for (int mt = 0; mt < 4; mt++)
                #pragma unroll
                for (int nt = 0; nt < 4; nt++) {
                    const uint32_t* bhf = &bh[nt >> 1][(nt & 1) * 2];
                    const uint32_t* blf = &bl[nt >> 1][(nt & 1) * 2];
                    mma16816(acc[mt][nt], ah[mt], bhf);
                    mma16816(acc[mt][nt], ah[mt], blf);
                    mma16816(acc[mt][nt], al[mt], bhf);
                }
        }
        if (kc + 2 < NKC) {
            __syncthreads();
            load_chunk(kc + 2, kc & 1);
        }
    }

    #pragma unroll
    for (int mt = 0; mt < 4; mt++) {
        int row0 = m0 + wm*64 + mt*16 + (lane >> 2);
        #pragma unroll
        for (int nt = 0; nt < 4; nt++) {
            int col = n0 + wn*32 + nt*8 + (lane & 3) * 2;
            float2 bi = *(const float2*)&bias[col];
            size_t o0 = (size_t)row0 * DD + col;
            size_t o1 = (size_t)(row0 + 8) * DD + col;
            float2 v0 = make_float2(acc[mt][nt][0] + bi.x, acc[mt][nt][1] + bi.y);
            float2 v1 = make_float2(acc[mt][nt][2] + bi.x, acc[mt][nt][3] + bi.y);
            if (resid) {
                float2 r0 = *(const float2*)(resid + o0);
                float2 r1 = *(const float2*)(resid + o1);
                v0.x += r0.x; v0.y += r0.y;
                v1.x += r1.x; v1.y += r1.y;
            }
            *(float2*)(C + o0) = v0;
            *(float2*)(C + o1) = v1;
        }
    }
}

// ---------- fwd: pack k+iv, one 1024-pt radix-2^2 FFT, 2 tokens/block ----------
__global__ void __launch_bounds__(512) fwd_kernel() {
    __shared__ float2 s0[2][1024];
    __shared__ float2 s1[2][1024];
    __shared__ float red[2][8];
    int tid = threadIdx.x;
    int half = tid >> 8, j = tid & 255;
    int t = blockIdx.x * 2 + half;

    const float* kr = g_keys + (size_t)t * DD;
    const float* vr = g_vals + (size_t)t * DD;
    float kv[4], vv[4];
    #pragma unroll
    for (int q = 0; q < 4; q++) { kv[q] = kr[j + q*256]; vv[q] = vr[j + q*256]; }

    float ss = kv[0]*kv[0] + kv[1]*kv[1] + kv[2]*kv[2] + kv[3]*kv[3];
    #pragma unroll
    for (int o = 16; o; o >>= 1) ss += __shfl_xor_sync(0xffffffffu, ss, o);
    if ((tid & 31) == 0) red[half][(tid >> 5) & 7] = ss;
    __syncthreads();
    float tot = 0.f;
    #pragma unroll
    for (int i = 0; i < 8; i++) tot += red[half][i];
    float scl = 1.0f / fmaxf(sqrtf(tot), 1e-12f);

    #pragma unroll
    for (int q = 0; q < 4; q++)
        s0[half][j + q*256] = make_float2(kv[q] * scl, vv[q]);
    __syncthreads();

    float2* Z = fft_r22<512, 1>(s0[half], s1[half], j, false);

    size_t fb = (size_t)t * FS;
    // bins: b = j (0..255), b = 512-j (257..512), plus b=256 on j==0
    #pragma unroll
    for (int sel = 0; sel < 2; sel++) {
        int b = sel ? (512 - j) : j;
        float2 za = Z[b];
        float2 zb = Z[(1024 - b) & 1023];
        float2 Kf = make_float2(0.5f * (za.x + zb.x), 0.5f * (za.y - zb.y));
        float2 dv = make_float2(za.x - zb.x, za.y + zb.y);
        float2 Vf = make_float2(0.5f * dv.y, -0.5f * dv.x);
        g_Kf[fb + b] = Kf;
        g_P [fb + b] = cmul(Kf, Vf);
    }
    if (j == 0) {
        float2 za = Z[256], zb = Z[768];
        float2 Kf = make_float2(0.5f * (za.x + zb.x), 0.5f * (za.y - zb.y));
        float2 dv = make_float2(za.x - zb.x, za.y + zb.y);
        float2 Vf = make_float2(0.5f * dv.y, -0.5f * dv.x);
        g_Kf[fb + 256] = Kf;
        g_P [fb + 256] = cmul(Kf, Vf);
    }
}

// ---------- scan pass 1: intra-chunk cumsum + chunk totals ----------
__global__ void __launch_bounds__(256) scan1() {
    int idx = blockIdx.x * blockDim.x + threadIdx.x;
    int comp  = idx % COMPS;
    int rest  = idx / COMPS;
    int chunk = rest % NCH;
    int b     = rest / NCH;
    float* Pf = (float*)g_P;
    size_t base = (size_t)(b * LL + chunk * CHL) * (FS * 2) + comp;
    float acc = 0.f;
    #pragma unroll 4
    for (int s = 0; s < CHL; s++) {
        acc += Pf[base];
        Pf[base] = acc;
        base += FS * 2;
    }
    g_aux[(b * NCH + chunk) * COMPS + comp] = acc;
}

// ---------- aux exclusive prefix scan (in place) ----------
__global__ void __launch_bounds__(256) aux_scan() {
    int idx = blockIdx.x * blockDim.x + threadIdx.x;
    if (idx >= BB * COMPS) return;
    int b = idx / COMPS, comp = idx % COMPS;
    float run = 0.f;
    for (int c = 0; c < NCH; c++) {
        size_t a = (size_t)(b * NCH + c) * COMPS + comp;
        float v = g_aux[a];
        g_aux[a] = run;
        run += v;
    }
}

// ---------- inv: unbind (+chunk offset), 512-pt radix-2^2 irfft, LN -> bf16 ----------
// 4 tokens per 512-thread block, 128 lanes each.
__global__ void __launch_bounds__(512) inv_kernel(const float* __restrict__ ln_g,
                                                  const float* __restrict__ ln_b) {
    __shared__ float2 sA[4][520];
    __shared__ float2 sB[4][512];
    __shared__ float red[4][8];
    int tid = threadIdx.x;
    int q = tid >> 7, j = tid & 127;
    int t = blockIdx.x * 4 + q;
    size_t fb = (size_t)t * FS;
    int bI = t >> 12;                   // t / LL
    int chunk = (t & (LL - 1)) >> 6;    // / CHL
    const float2* aux2 = (const float2*)g_aux + (size_t)(bI * NCH + chunk) * (COMPS/2);

    // S[k] = (P_partial[k] + aux[k]) * conj(Kf[k])
    #pragma unroll
    for (int p = 0; p < 4; p++) {
        int k = j + p * 128;
        float2 kf = g_Kf[fb + k];
        float2 mp = g_P [fb + k];
        float2 av = aux2[k];
        mp.x += av.x; mp.y += av.y;
        sA[q][k] = make_float2(mp.x*kf.x + mp.y*kf.y, mp.y*kf.x - mp.x*kf.y);
    }
    if (j == 0) {
        float2 kf = g_Kf[fb + 512];
        float2 mp = g_P [fb + 512];
        float2 av = aux2[512];
        mp.x += av.x; mp.y += av.y;
        sA[q][512] = make_float2(mp.x*kf.x + mp.y*kf.y, mp.y*kf.x - mp.x*kf.y);
    }
    __syncthreads();

    // Zf[k] = Xe + i*Xo,  Xo = (S[k]-conj(S[512-k]))/2 * e^{+2pi i k/1024}
    #pragma unroll
    for (int p = 0; p < 4; p++) {
        int k = j + p * 128;
        float2 Sa = sA[q][k];
        float2 Sb = sA[q][512 - k];
        float2 tw = g_twid[k];
        float twx = tw.x, twy = -tw.y;
        float2 Xe = make_float2(0.5f*(Sa.x + Sb.x), 0.5f*(Sa.y - Sb.y));
        float2 Xd = make_float2(0.5f*(Sa.x - Sb.x), 0.5f*(Sa.y + Sb.y));
        float2 Xo = make_float2(Xd.x*twx - Xd.y*twy, Xd.x*twy + Xd.y*twx);
        sB[q][k] = make_float2(Xe.x - Xo.y, Xe.y + Xo.x);
    }
    __syncthreads();

    float2* R = fft_r22<256, 2>(sB[q], sA[q], j, true);   // 4 double-stages

    // final twiddle-free radix-2 (m=256) in registers
    float2 Ra = R[j], Rb = R[j + 256], Rc = R[j + 128], Rd = R[j + 384];
    float2 z[4];
    int    zi[4];
    z[0] = cadd(Ra, Rb); zi[0] = j;
    z[1] = csub(Ra, Rb); zi[1] = j + 256;
    z[2] = cadd(Rc, Rd); zi[2] = j + 128;
    z[3] = csub(Rc, Rd); zi[3] = j + 384;

    int pos = (t & (LL - 1)) + 1;
    float scale = rsqrtf((float)pos) * (1.0f / 512.0f);
    float r[8];
    #pragma unroll
    for (int p = 0; p < 4; p++) { r[2*p] = z[p].x * scale; r[2*p+1] = z[p].y * scale; }

    float sm = 0.f, sq = 0.f;
    #pragma unroll
    for (int p = 0; p < 8; p++) { sm += r[p]; sq += r[p]*r[p]; }
    #pragma unroll
    for (int o = 16; o; o >>= 1) {
        sm += __shfl_xor_sync(0xffffffffu, sm, o);
        sq += __shfl_xor_sync(0xffffffffu, sq, o);
    }
    int w4 = (tid >> 5) & 3;
    if ((tid & 31) == 0) { red[q][w4] = sm; red[q][4 + w4] = sq; }
    __syncthreads();
    float smT = 0.f, sqT = 0.f;
    #pragma unroll
    for (int i = 0; i < 4; i++) { smT += red[q][i]; sqT += red[q][4 + i]; }
    float mu  = smT * (1.0f / 1024.0f);
    float var = sqT * (1.0f / 1024.0f) - mu * mu;
    float rstd = rsqrtf(var + 1e-5f);

    __nv_bfloat162* RH = (__nv_bfloat162*)g_rh;
    __nv_bfloat162* RL = (__nv_bfloat162*)g_rl;
    size_t hb = (size_t)t * 512;
    #pragma unroll
    for (int p = 0; p < 4; p++) {
        int idx = zi[p];
        float2 gg = *(const float2*)&ln_g[2*idx];
        float2 bb = *(const float2*)&ln_b[2*idx];
        float y0 = (r[2*p]   - mu) * rstd * gg.x + bb.x;
        float y1 = (r[2*p+1] - mu) * rstd * gg.y + bb.y;
        __nv_bfloat16 h0 = __float2bfloat16_rn(y0);
        __nv_bfloat16 h1 = __float2bfloat16_rn(y1);
        RH[hb + idx] = __nv_bfloat162(h0, h1);
        RL[hb + idx] = __nv_bfloat162(__float2bfloat16_rn(y0 - __bfloat162float(h0)),
                                      __float2bfloat16_rn(y1 - __bfloat162float(h1)));
    }
}

// ---------- launch ----------
extern "C" void kernel_launch(void* const* d_in, const int* in_sizes, int n_in,
                              void* d_out, int out_size) {
    const float* x    = (const float*)d_in[0];
    const float* Wk   = (const float*)d_in[1];
    const float* bk   = (const float*)d_in[2];
    const float* Wv   = (const float*)d_in[3];
    const float* bv   = (const float*)d_in[4];
    const float* ln_g = (const float*)d_in[5];
    const float* ln_b = (const float*)d_in[6];
    const float* Wo   = (const float*)d_in[7];
    const float* bo   = (const float*)d_in[8];
    float* out = (float*)d_out;

    float *keys, *vals;
    __nv_bfloat16 *xh, *xl, *rh, *rl, *wkh, *wkl, *wvh, *wvl, *woh, *wol;
    cudaGetSymbolAddress((void**)&keys, g_keys);
    cudaGetSymbolAddress((void**)&vals, g_vals);
    cudaGetSymbolAddress((void**)&xh, g_xh);   cudaGetSymbolAddress((void**)&xl, g_xl);
    cudaGetSymbolAddress((void**)&rh, g_rh);   cudaGetSymbolAddress((void**)&rl, g_rl);
    cudaGetSymbolAddress((void**)&wkh, g_Wkh); cudaGetSymbolAddress((void**)&wkl, g_Wkl);
    cudaGetSymbolAddress((void**)&wvh, g_Wvh); cudaGetSymbolAddress((void**)&wvl, g_Wvl);
    cudaGetSymbolAddress((void**)&woh, g_Woh); cudaGetSymbolAddress((void**)&wol, g_Wol);

    cudaFuncSetAttribute(gemm_bf16, cudaFuncAttributeMaxDynamicSharedMemorySize, GEMM_SMEM);

    init_twid<<<1, 512>>>();

    conv_split<<<(NT*DD/4 + 255)/256, 256>>>(x,  xh,  xl,  NT*DD/4);
    conv_split<<<(DD*DD/4 + 255)/256, 256>>>(Wk, wkh, wkl, DD*DD/4);
    conv_split<<<(DD*DD/4 + 255)/256, 256>>>(Wv, wvh, wvl, DD*DD/4);
    conv_split<<<(DD*DD/4 + 255)/256, 256>>>(Wo, woh, wol, DD*DD/4);

    dim3 gg(8, NT / TM);  // (8, 128)
    gemm_bf16<<<gg, 256, GEMM_SMEM>>>(xh, xl, wkh, wkl, bk, nullptr, keys);
    gemm_bf16<<<gg, 256, GEMM_SMEM>>>(xh, xl, wvh, wvl, bv, nullptr, vals);

    fwd_kernel<<<NT/2, 512>>>();

    scan1<<<(BB * NCH * COMPS) / 256, 256>>>();
    aux_scan<<<(BB * COMPS + 255) / 256, 256>>>();

    inv_kernel<<<NT/4, 512>>>(ln_g, ln_b);

    gemm_bf16<<<gg, 256, GEMM_SMEM>>>(rh, rl, woh, wol, bo, x, out);
}